// round 6
// baseline (speedup 1.0000x reference)
#include <cuda_runtime.h>
#include <math.h>

// x (B=32, C=256, H=64, W=64) fp32; s=mean_c(x); h=relu(s*w1+b1)[16];
// scale=sigmoid(w2@h+b2); out=x*scale
// Identity: z[c] = w2[c]@relu(s*w1+b1)+b2[c] is piecewise-linear in s:
//   z[c] = A[c,i]*s + B[c,i],  i = #{k : s > t_k},  t_k = -b1[k]/w1[k]
// R6: 128-px tiles, one channel-group per warp (coalesced), x held in regs
// (v[16]), SoA+pad smem partials, all-thread shuffle-butterfly reduce,
// 2 barriers/tile, persistent grid 148, 1 CTA/SM.

#define B_    32
#define CH    256
#define HW4   1024          // 4096/4 float4 per (b,c) row
#define HID   16
#define P4    32            // float4 pixels per tile (128 px)
#define TPB   512
#define NGRP  16            // warps per CTA = channel groups
#define CPT   16            // channels per thread
#define NTILE 1024          // 32 images * (1024/32) tiles
#define GRID  148
#define RPAD  33            // SoA row pad: conflict-free reads+writes

__global__ __launch_bounds__(TPB, 1)
void pse_fused_kernel(const float4* __restrict__ x,
                      const float*  __restrict__ w1,
                      const float*  __restrict__ b1,
                      const float*  __restrict__ w2,
                      const float*  __restrict__ b2,
                      float4* __restrict__ out)
{
    __shared__ float2 AB[CH * 17];          // 34,816 B piecewise-linear table
    __shared__ float  red_x[NGRP * RPAD];   // SoA partials, padded
    __shared__ float  red_y[NGRP * RPAD];
    __shared__ float  red_z[NGRP * RPAD];
    __shared__ float  red_w[NGRP * RPAD];
    __shared__ float4 s4b[P4];
    __shared__ int4   i4b[P4];
    __shared__ float  us[HID];
    __shared__ float  reps[HID + 1];

    const int t = threadIdx.x;
    const int q = t & 31;                   // pixel-col within tile
    const int g = t >> 5;                   // warp = channel group
    const float INF = __int_as_float(0x7f800000);

    // ---------- per-CTA prologue: build piecewise-linear table ----------
    if (t < HID) {
        float w = w1[t], b = b1[t];
        float myth = (w != 0.0f) ? (-b / w) : INF;
        int rank = 0;
        #pragma unroll
        for (int k = 0; k < HID; k++) {
            float wk = w1[k], bk = b1[k];
            float tk = (wk != 0.0f) ? (-bk / wk) : INF;
            rank += (tk < myth) || (tk == myth && k < t);
        }
        us[rank] = myth;
    }
    __syncthreads();
    if (t < HID + 1) {
        float lo = (t == 0)   ? -INF : us[t - 1];
        float hi = (t == HID) ?  INF : us[t];
        bool flo = isfinite(lo), fhi = isfinite(hi);
        if (!flo && !fhi)      { lo = -1.0f; hi = 1.0f; }
        else if (!flo)         lo = hi - 2.0f;
        else if (!fhi)         hi = lo + 2.0f;
        reps[t] = 0.5f * (lo + hi);
    }
    __syncthreads();
    if (t < CH) {
        const int c = t;
        float w2r[HID];
        #pragma unroll
        for (int k = 0; k < HID; k++) w2r[k] = w2[c * HID + k];
        const float bc = b2[c];
        for (int i = 0; i < 17; i++) {
            const float rep = reps[i];
            float a = 0.0f, bb = bc;
            #pragma unroll
            for (int k = 0; k < HID; k++) {
                float wk = w1[k], bk = b1[k];
                if (fmaf(rep, wk, bk) > 0.0f) {   // unit k active on interval i
                    a  = fmaf(w2r[k], wk, a);
                    bb = fmaf(w2r[k], bk, bb);
                }
            }
            AB[c * 17 + i] = make_float2(a, bb);
        }
    }
    __syncthreads();

    // ---------- persistent tile loop ----------
    for (int tile = blockIdx.x; tile < NTILE; tile += GRID) {
        const int img   = tile >> 5;            // 32 tiles per image
        const int base4 = (tile & 31) << 5;     // float4-col base
        const float4* xb = x   + (size_t)img * CH * HW4 + base4;
        float4*       ob = out + (size_t)img * CH * HW4 + base4;

        // pass 1: 16 independent coalesced LDG.128 per thread, kept in regs
        float4 v[CPT];
        #pragma unroll
        for (int j = 0; j < CPT; j++)
            v[j] = __ldcs(&xb[(g + j * NGRP) * HW4 + q]);

        float4 s = make_float4(0.f, 0.f, 0.f, 0.f);
        #pragma unroll
        for (int j = 0; j < CPT; j++) {
            s.x += v[j].x; s.y += v[j].y; s.z += v[j].z; s.w += v[j].w;
        }
        red_x[g * RPAD + q] = s.x;   // bank = (g+q)&31: conflict-free
        red_y[g * RPAD + q] = s.y;
        red_z[g * RPAD + q] = s.z;
        red_w[g * RPAD + q] = s.w;
        __syncthreads();

        // stage 2: ALL 512 threads. q2 = t>>4 (pixel), g2 = t&15 (group).
        // 16 consecutive lanes share q2 -> butterfly xor {1,2,4,8}.
        {
            const int q2 = t >> 4, g2 = t & 15;
            float ax = red_x[g2 * RPAD + q2];   // bank (g2+q2)&31: c-free
            float ay = red_y[g2 * RPAD + q2];
            float az = red_z[g2 * RPAD + q2];
            float aw = red_w[g2 * RPAD + q2];
            #pragma unroll
            for (int m = 1; m <= 8; m <<= 1) {
                ax += __shfl_xor_sync(0xffffffffu, ax, m);
                ay += __shfl_xor_sync(0xffffffffu, ay, m);
                az += __shfl_xor_sync(0xffffffffu, az, m);
                aw += __shfl_xor_sync(0xffffffffu, aw, m);
            }
            if (g2 == 0) {
                const float inv = 1.0f / (float)CH;
                float4 sv = make_float4(ax * inv, ay * inv, az * inv, aw * inv);
                int4 iv = make_int4(0, 0, 0, 0);
                #pragma unroll
                for (int k = 0; k < HID; k++) {
                    const float tk = us[k];
                    iv.x += (sv.x > tk); iv.y += (sv.y > tk);
                    iv.z += (sv.z > tk); iv.w += (sv.w > tk);
                }
                s4b[q2] = sv; i4b[q2] = iv;
            }
        }
        __syncthreads();

        // pass 2: pure compute from registers + smem table, then store
        const float4 sv = s4b[q];
        const int4   iv = i4b[q];
        #pragma unroll
        for (int j = 0; j < CPT; j++) {
            const int c = g + j * NGRP;
            const float2* row = AB + c * 17;
            const float2 a0 = row[iv.x], a1 = row[iv.y],
                         a2 = row[iv.z], a3 = row[iv.w];
            const float z0 = fmaf(a0.x, sv.x, a0.y);
            const float z1 = fmaf(a1.x, sv.y, a1.y);
            const float z2 = fmaf(a2.x, sv.z, a2.y);
            const float z3 = fmaf(a3.x, sv.w, a3.y);
            float4 o;
            o.x = __fdividef(v[j].x, 1.0f + __expf(-z0));
            o.y = __fdividef(v[j].y, 1.0f + __expf(-z1));
            o.z = __fdividef(v[j].z, 1.0f + __expf(-z2));
            o.w = __fdividef(v[j].w, 1.0f + __expf(-z3));
            __stcs(&ob[c * HW4 + q], o);
        }
        // next tile's smem writes are fenced by its own __syncthreads()
    }
}

extern "C" void kernel_launch(void* const* d_in, const int* in_sizes, int n_in,
                              void* d_out, int out_size)
{
    pse_fused_kernel<<<GRID, TPB>>>((const float4*)d_in[0],
                                    (const float*)d_in[1],
                                    (const float*)d_in[2],
                                    (const float*)d_in[3],
                                    (const float*)d_in[4],
                                    (float4*)d_out);
}

// round 7
// speedup vs baseline: 1.1719x; 1.1719x over previous
#include <cuda_runtime.h>
#include <math.h>

// x (B=32, C=256, H=64, W=64) fp32; s=mean_c(x); h=relu(s*w1+b1)[16];
// scale=sigmoid(w2@h+b2); out=x*scale
// Identity: z[c] = w2[c]@relu(s*w1+b1)+b2[c] is piecewise-linear in s:
//   z[c] = A[c,i]*s + B[c,i],  i = #{k : s > t_k},  t_k = -b1[k]/w1[k]
// R7: 4 small independent CTAs/SM (256 thr, 8 warps) so barriers stall only
// 1/4 of resident warps; CPT=8 reg-held x keeps 131KB/SM in flight; full
// 256-thread butterfly reduce; persistent grid, smem AB table.

#define B_    32
#define CH    256
#define HW4   1024          // 4096/4 float4 per (b,c) row
#define HID   16
#define P4    8             // float4 pixels per tile (32 px)
#define TPB   256
#define NGRP  32            // channel groups
#define CPT   8             // channels per thread -> v[8] = 32 regs
#define NTILE 4096          // 32 images * (1024/8) tiles
#define GRID  592           // 4 persistent CTAs per SM * 148
#define RPAD  9             // partials row pad (odd stride: c-free reads)

__global__ __launch_bounds__(TPB, 4)
void pse_fused_kernel(const float4* __restrict__ x,
                      const float*  __restrict__ w1,
                      const float*  __restrict__ b1,
                      const float*  __restrict__ w2,
                      const float*  __restrict__ b2,
                      float4* __restrict__ out)
{
    __shared__ float2 AB[CH * 17];          // 34,816 B piecewise-linear table
    __shared__ float  red_x[NGRP * RPAD];   // SoA partials [group][pixel]
    __shared__ float  red_y[NGRP * RPAD];
    __shared__ float  red_z[NGRP * RPAD];
    __shared__ float  red_w[NGRP * RPAD];
    __shared__ float4 s4b[P4];
    __shared__ int4   i4b[P4];
    __shared__ float  us[HID];
    __shared__ float  reps[HID + 1];

    const int t = threadIdx.x;
    const int q = t & (P4 - 1);             // float4-pixel 0..7
    const int g = t >> 3;                   // channel group 0..31
    const float INF = __int_as_float(0x7f800000);

    // ---------- per-CTA prologue: build piecewise-linear table ----------
    if (t < HID) {
        float w = w1[t], b = b1[t];
        float myth = (w != 0.0f) ? (-b / w) : INF;
        int rank = 0;
        #pragma unroll
        for (int k = 0; k < HID; k++) {
            float wk = w1[k], bk = b1[k];
            float tk = (wk != 0.0f) ? (-bk / wk) : INF;
            rank += (tk < myth) || (tk == myth && k < t);
        }
        us[rank] = myth;
    }
    __syncthreads();
    if (t < HID + 1) {
        float lo = (t == 0)   ? -INF : us[t - 1];
        float hi = (t == HID) ?  INF : us[t];
        bool flo = isfinite(lo), fhi = isfinite(hi);
        if (!flo && !fhi)      { lo = -1.0f; hi = 1.0f; }
        else if (!flo)         lo = hi - 2.0f;
        else if (!fhi)         hi = lo + 2.0f;
        reps[t] = 0.5f * (lo + hi);
    }
    __syncthreads();
    {   // one channel per thread (TPB == CH)
        const int c = t;
        float w2r[HID];
        #pragma unroll
        for (int k = 0; k < HID; k++) w2r[k] = w2[c * HID + k];
        const float bc = b2[c];
        for (int i = 0; i < 17; i++) {
            const float rep = reps[i];
            float a = 0.0f, bb = bc;
            #pragma unroll
            for (int k = 0; k < HID; k++) {
                float wk = w1[k], bk = b1[k];
                if (fmaf(rep, wk, bk) > 0.0f) {   // unit k active on interval i
                    a  = fmaf(w2r[k], wk, a);
                    bb = fmaf(w2r[k], bk, bb);
                }
            }
            AB[c * 17 + i] = make_float2(a, bb);
        }
    }
    __syncthreads();

    // ---------- persistent tile loop ----------
    for (int tile = blockIdx.x; tile < NTILE; tile += GRID) {
        const int img   = tile >> 7;            // 128 tiles per image
        const int base4 = (tile & 127) << 3;    // float4-col base
        const float4* xb = x   + (size_t)img * CH * HW4 + base4;
        float4*       ob = out + (size_t)img * CH * HW4 + base4;

        // pass 1: 8 independent LDG.128 into registers (kept live) + sums
        float4 v[CPT];
        #pragma unroll
        for (int j = 0; j < CPT; j++)
            v[j] = __ldcs(&xb[(g + j * NGRP) * HW4 + q]);

        float4 s = make_float4(0.f, 0.f, 0.f, 0.f);
        #pragma unroll
        for (int j = 0; j < CPT; j++) {
            s.x += v[j].x; s.y += v[j].y; s.z += v[j].z; s.w += v[j].w;
        }
        red_x[g * RPAD + q] = s.x;
        red_y[g * RPAD + q] = s.y;
        red_z[g * RPAD + q] = s.z;
        red_w[g * RPAD + q] = s.w;
        __syncthreads();

        // all-thread reduce: warp w owns pixel w (8 warps = 8 pixels),
        // lane l reads group-l partial; 5-step butterfly; lane 0 classifies.
        {
            const int w = t >> 5, l = t & 31;
            float ax = red_x[l * RPAD + w];   // stride 9 (odd): conflict-free
            float ay = red_y[l * RPAD + w];
            float az = red_z[l * RPAD + w];
            float aw = red_w[l * RPAD + w];
            #pragma unroll
            for (int m = 1; m <= 16; m <<= 1) {
                ax += __shfl_xor_sync(0xffffffffu, ax, m);
                ay += __shfl_xor_sync(0xffffffffu, ay, m);
                az += __shfl_xor_sync(0xffffffffu, az, m);
                aw += __shfl_xor_sync(0xffffffffu, aw, m);
            }
            if (l == 0) {
                const float inv = 1.0f / (float)CH;
                float4 sv = make_float4(ax * inv, ay * inv, az * inv, aw * inv);
                int4 iv = make_int4(0, 0, 0, 0);
                #pragma unroll
                for (int k = 0; k < HID; k++) {
                    const float tk = us[k];
                    iv.x += (sv.x > tk); iv.y += (sv.y > tk);
                    iv.z += (sv.z > tk); iv.w += (sv.w > tk);
                }
                s4b[w] = sv; i4b[w] = iv;
            }
        }
        __syncthreads();

        // pass 2: pure compute from registers + smem table, then store
        const float4 sv = s4b[q];
        const int4   iv = i4b[q];
        #pragma unroll
        for (int j = 0; j < CPT; j++) {
            const int c = g + j * NGRP;
            const float2* row = AB + c * 17;
            const float2 a0 = row[iv.x], a1 = row[iv.y],
                         a2 = row[iv.z], a3 = row[iv.w];
            const float z0 = fmaf(a0.x, sv.x, a0.y);
            const float z1 = fmaf(a1.x, sv.y, a1.y);
            const float z2 = fmaf(a2.x, sv.z, a2.y);
            const float z3 = fmaf(a3.x, sv.w, a3.y);
            float4 o;
            o.x = __fdividef(v[j].x, 1.0f + __expf(-z0));
            o.y = __fdividef(v[j].y, 1.0f + __expf(-z1));
            o.z = __fdividef(v[j].z, 1.0f + __expf(-z2));
            o.w = __fdividef(v[j].w, 1.0f + __expf(-z3));
            __stcs(&ob[c * HW4 + q], o);
        }
        // next tile's smem writes are fenced by its own __syncthreads()
    }
}

extern "C" void kernel_launch(void* const* d_in, const int* in_sizes, int n_in,
                              void* d_out, int out_size)
{
    pse_fused_kernel<<<GRID, TPB>>>((const float4*)d_in[0],
                                    (const float*)d_in[1],
                                    (const float*)d_in[2],
                                    (const float*)d_in[3],
                                    (const float*)d_in[4],
                                    (float4*)d_out);
}